// round 7
// baseline (speedup 1.0000x reference)
#include <cuda_runtime.h>
#include <cuda_bf16.h>
#include <cstdint>

// Problem constants
#define N_NODES 100000
#define N_EDGES 1638400
#define IN_CH   128
#define HEADS   4
#define OUT_CH  32
#define OUTF    (HEADS * OUT_CH)   // 128

// Scratch (allowed: __device__ globals, no allocation)
__device__ float g_h [(size_t)N_NODES * OUTF];   // 51.2 MB, L2-resident
__device__ float g_al[(size_t)N_NODES * HEADS];
__device__ float g_ar[(size_t)N_NODES * HEADS];

// ---------------------------------------------------------------------------
// Kernel 1: h = x @ W^T + b   (M=100000, K=128, N=128), fp32 FFMA GEMM
// BM=128, BN=128, BK=32, 256 threads, 8x8 microtile per thread.
// Epilogue additionally computes per-node attention scores
//   alpha_l[n][head] = dot(h[n, head*32:(head+1)*32], att_l[head*32:...])
// (thread tx owns cols tx*8..tx*8+7, which lie inside head tx>>2, so a
//  4-way tx-group reduction per head suffices; smem tiles reused as scratch)
// ---------------------------------------------------------------------------
#define BM 128
#define BN 128
#define BK 32
#define TM 8
#define TN 8

__global__ __launch_bounds__(256, 2)
void gemm_proj_kernel(const float* __restrict__ x,
                      const float* __restrict__ W,
                      const float* __restrict__ b,
                      const float* __restrict__ att_l,
                      const float* __restrict__ att_r,
                      int nrows)
{
    __shared__ float Xs[BK][BM];   // k-major; reused as partL in epilogue
    __shared__ float Ws[BK][BN];   // k-major; reused as partR in epilogue

    const int tid = threadIdx.x;
    const int tx  = tid & 15;          // 0..15  (output-col group)
    const int ty  = tid >> 4;          // 0..15  (output-row group)
    const int row0 = blockIdx.x * BM;

    float acc[TM][TN] = {};

    for (int kt = 0; kt < IN_CH; kt += BK) {
        // ---- load X tile: rows [row0, row0+128), cols [kt, kt+32) -> Xs[k][m]
        #pragma unroll
        for (int l = tid; l < BM * (BK / 4); l += 256) {   // 1024 float4 loads
            int m = l >> 3;
            int j = l & 7;
            int grow = row0 + m;
            float4 v = make_float4(0.f, 0.f, 0.f, 0.f);
            if (grow < nrows)
                v = *reinterpret_cast<const float4*>(x + (size_t)grow * IN_CH + kt + j * 4);
            Xs[j * 4 + 0][m] = v.x;
            Xs[j * 4 + 1][m] = v.y;
            Xs[j * 4 + 2][m] = v.z;
            Xs[j * 4 + 3][m] = v.w;
        }
        // ---- load W tile: W[o][k], o in [0,128), k in [kt,kt+32) -> Ws[k][o]
        #pragma unroll
        for (int l = tid; l < BN * (BK / 4); l += 256) {
            int o = l >> 3;
            int j = l & 7;
            float4 v = *reinterpret_cast<const float4*>(W + (size_t)o * IN_CH + kt + j * 4);
            Ws[j * 4 + 0][o] = v.x;
            Ws[j * 4 + 1][o] = v.y;
            Ws[j * 4 + 2][o] = v.z;
            Ws[j * 4 + 3][o] = v.w;
        }
        __syncthreads();

        #pragma unroll 8
        for (int k = 0; k < BK; k++) {
            float xf[TM], wf[TN];
            *reinterpret_cast<float4*>(&xf[0]) = *reinterpret_cast<const float4*>(&Xs[k][ty * TM + 0]);
            *reinterpret_cast<float4*>(&xf[4]) = *reinterpret_cast<const float4*>(&Xs[k][ty * TM + 4]);
            *reinterpret_cast<float4*>(&wf[0]) = *reinterpret_cast<const float4*>(&Ws[k][tx * TN + 0]);
            *reinterpret_cast<float4*>(&wf[4]) = *reinterpret_cast<const float4*>(&Ws[k][tx * TN + 4]);
            #pragma unroll
            for (int i = 0; i < TM; i++)
                #pragma unroll
                for (int j = 0; j < TN; j++)
                    acc[i][j] += xf[i] * wf[j];
        }
        __syncthreads();   // after last iter: tiles dead, safe to reuse below
    }

    // ---- epilogue: add bias, store h, compute per-head alpha partials
    float bias[TN], attl[TN], attr[TN];
    *reinterpret_cast<float4*>(&bias[0]) = *reinterpret_cast<const float4*>(b + tx * TN + 0);
    *reinterpret_cast<float4*>(&bias[4]) = *reinterpret_cast<const float4*>(b + tx * TN + 4);
    *reinterpret_cast<float4*>(&attl[0]) = *reinterpret_cast<const float4*>(att_l + tx * TN + 0);
    *reinterpret_cast<float4*>(&attl[4]) = *reinterpret_cast<const float4*>(att_l + tx * TN + 4);
    *reinterpret_cast<float4*>(&attr[0]) = *reinterpret_cast<const float4*>(att_r + tx * TN + 0);
    *reinterpret_cast<float4*>(&attr[4]) = *reinterpret_cast<const float4*>(att_r + tx * TN + 4);

    float* partL = &Xs[0][0];   // [128][16] partial alpha_l
    float* partR = &Ws[0][0];   // [128][16] partial alpha_r

    #pragma unroll
    for (int i = 0; i < TM; i++) {
        int lrow = ty * TM + i;
        int grow = row0 + lrow;
        float vsum[TN];
        float pl = 0.f, pr = 0.f;
        #pragma unroll
        for (int j = 0; j < TN; j++) {
            vsum[j] = acc[i][j] + bias[j];
            pl += vsum[j] * attl[j];
            pr += vsum[j] * attr[j];
        }
        partL[lrow * 16 + tx] = pl;
        partR[lrow * 16 + tx] = pr;
        if (grow < nrows) {
            *reinterpret_cast<float4*>(g_h + (size_t)grow * OUTF + tx * TN + 0) =
                make_float4(vsum[0], vsum[1], vsum[2], vsum[3]);
            *reinterpret_cast<float4*>(g_h + (size_t)grow * OUTF + tx * TN + 4) =
                make_float4(vsum[4], vsum[5], vsum[6], vsum[7]);
        }
    }
    __syncthreads();

    // reduce 4 tx-groups per (row, head); 512 outputs per side
    #pragma unroll
    for (int o = tid; o < BM * HEADS; o += 256) {
        int lrow = o >> 2;
        int head = o & 3;
        int grow = row0 + lrow;
        if (grow < nrows) {
            float sl = 0.f, sr = 0.f;
            #pragma unroll
            for (int t = 0; t < 4; t++) {
                sl += partL[lrow * 16 + head * 4 + t];
                sr += partR[lrow * 16 + head * 4 + t];
            }
            g_al[(size_t)grow * HEADS + head] = sl;
            g_ar[(size_t)grow * HEADS + head] = sr;
        }
    }
}

// ---------------------------------------------------------------------------
// Kernel 2: edge lift. Persistent grid-stride; 4 edges per warp per iter.
// Lanes 0..3 fetch src/trg indices (broadcast via shuffle), 4 independent
// 512B row gathers issued back-to-back (MLP=4), streaming stores.
// Alpha: lane u<4 owns edge base+u -> float4 load/leaky/store.
// ---------------------------------------------------------------------------
__global__ __launch_bounds__(256)
void edge_lift_kernel(const int* __restrict__ src_idx,
                      const int* __restrict__ trg_idx,
                      float* __restrict__ out_alpha,
                      float* __restrict__ out_x,
                      int nedges)
{
    const int lane   = threadIdx.x & 31;
    const int nwarps = (gridDim.x * blockDim.x) >> 5;
    const int gw     = (blockIdx.x * blockDim.x + threadIdx.x) >> 5;

    // N_EDGES % 4 == 0 and stride % 4 == 0 -> every group of 4 is fully valid
    for (long long base = (long long)gw * 4; base < nedges;
         base += (long long)nwarps * 4) {

        int sidx = 0, tidx = 0;
        if (lane < 4) {
            sidx = __ldg(src_idx + base + lane);
            tidx = __ldg(trg_idx + base + lane);
        }
        int s0 = __shfl_sync(0xffffffffu, sidx, 0);
        int s1 = __shfl_sync(0xffffffffu, sidx, 1);
        int s2 = __shfl_sync(0xffffffffu, sidx, 2);
        int s3 = __shfl_sync(0xffffffffu, sidx, 3);

        // 4 independent gathers (compiler batches these -> MLP=4)
        float4 v0 = *reinterpret_cast<const float4*>(g_h + (size_t)s0 * OUTF + lane * 4);
        float4 v1 = *reinterpret_cast<const float4*>(g_h + (size_t)s1 * OUTF + lane * 4);
        float4 v2 = *reinterpret_cast<const float4*>(g_h + (size_t)s2 * OUTF + lane * 4);
        float4 v3 = *reinterpret_cast<const float4*>(g_h + (size_t)s3 * OUTF + lane * 4);

        __stcs(reinterpret_cast<float4*>(out_x + (base + 0) * OUTF + lane * 4), v0);
        __stcs(reinterpret_cast<float4*>(out_x + (base + 1) * OUTF + lane * 4), v1);
        __stcs(reinterpret_cast<float4*>(out_x + (base + 2) * OUTF + lane * 4), v2);
        __stcs(reinterpret_cast<float4*>(out_x + (base + 3) * OUTF + lane * 4), v3);

        if (lane < 4) {
            float4 al = *reinterpret_cast<const float4*>(g_al + (size_t)sidx * HEADS);
            float4 ar = *reinterpret_cast<const float4*>(g_ar + (size_t)tidx * HEADS);
            float4 a;
            a.x = al.x + ar.x; a.x = (a.x >= 0.f) ? a.x : 0.01f * a.x;
            a.y = al.y + ar.y; a.y = (a.y >= 0.f) ? a.y : 0.01f * a.y;
            a.z = al.z + ar.z; a.z = (a.z >= 0.f) ? a.z : 0.01f * a.z;
            a.w = al.w + ar.w; a.w = (a.w >= 0.f) ? a.w : 0.01f * a.w;
            __stcs(reinterpret_cast<float4*>(out_alpha + (base + lane) * HEADS), a);
        }
    }
}

// ---------------------------------------------------------------------------
// Launch
// ---------------------------------------------------------------------------
extern "C" void kernel_launch(void* const* d_in, const int* in_sizes, int n_in,
                              void* d_out, int out_size)
{
    const float* x     = (const float*)d_in[0];   // [N, 128]
    const float* W     = (const float*)d_in[1];   // [128, 128]
    const float* b     = (const float*)d_in[2];   // [128]
    const float* att_l = (const float*)d_in[3];   // [1,4,32] -> flat 128
    const float* att_r = (const float*)d_in[4];   // [1,4,32] -> flat 128
    const int*   src   = (const int*)d_in[5];     // [E]
    const int*   trg   = (const int*)d_in[6];     // [E]

    float* out_alpha = (float*)d_out;                                   // [E, 4]
    float* out_x     = (float*)d_out + (size_t)N_EDGES * HEADS;         // [E, 4, 32]

    // 1) projection GEMM into g_h (+ fused alpha_l/alpha_r)
    int gemm_blocks = (N_NODES + BM - 1) / BM;                 // 782
    gemm_proj_kernel<<<gemm_blocks, 256>>>(x, W, b, att_l, att_r, N_NODES);

    // 2) edge lift: persistent, 8 CTAs/SM
    int edge_blocks = 148 * 8;                                 // 1184
    edge_lift_kernel<<<edge_blocks, 256>>>(src, trg, out_alpha, out_x, N_EDGES);
}

// round 8
// speedup vs baseline: 1.1120x; 1.1120x over previous
#include <cuda_runtime.h>
#include <cuda_bf16.h>
#include <cstdint>

// Problem constants
#define N_NODES 100000
#define N_EDGES 1638400
#define IN_CH   128
#define HEADS   4
#define OUT_CH  32
#define OUTF    (HEADS * OUT_CH)   // 128

// Scratch (allowed: __device__ globals, no allocation)
__device__ float g_h [(size_t)N_NODES * OUTF];   // 51.2 MB, L2-resident
__device__ float g_al[(size_t)N_NODES * HEADS];
__device__ float g_ar[(size_t)N_NODES * HEADS];

// ---------------------------------------------------------------------------
// Packed f32x2 FMA (sm_100+): 2 MACs per fma-pipe issue slot.
// ---------------------------------------------------------------------------
__device__ __forceinline__ void fma_f32x2(unsigned long long& d,
                                          unsigned long long a,
                                          unsigned long long b) {
    asm("fma.rn.f32x2 %0, %1, %2, %0;" : "+l"(d) : "l"(a), "l"(b));
}
__device__ __forceinline__ unsigned long long bcast2(float v) {
    unsigned long long r;
    unsigned u = __float_as_uint(v);
    asm("mov.b64 %0, {%1, %1};" : "=l"(r) : "r"(u));
    return r;
}
__device__ __forceinline__ void unpack2(unsigned long long v, float& lo, float& hi) {
    unsigned a, b;
    asm("mov.b64 {%0, %1}, %2;" : "=r"(a), "=r"(b) : "l"(v));
    lo = __uint_as_float(a);
    hi = __uint_as_float(b);
}

// ---------------------------------------------------------------------------
// Kernel 1: h = x @ W^T + b   (M=100000, K=128, N=128)
// BM=128, BN=128, BK=32, 256 threads, 8x8 microtile, FFMA2 microloop.
// Epilogue fuses per-node attention scores alpha_l / alpha_r.
// ---------------------------------------------------------------------------
#define BM 128
#define BN 128
#define BK 32
#define TM 8
#define TN 8

__global__ __launch_bounds__(256, 2)
void gemm_proj_kernel(const float* __restrict__ x,
                      const float* __restrict__ W,
                      const float* __restrict__ b,
                      const float* __restrict__ att_l,
                      const float* __restrict__ att_r,
                      int nrows)
{
    __shared__ __align__(16) float Xs[BK][BM];   // k-major; reused in epilogue
    __shared__ __align__(16) float Ws[BK][BN];   // k-major; reused in epilogue

    const int tid = threadIdx.x;
    const int tx  = tid & 15;          // 0..15  (output-col group)
    const int ty  = tid >> 4;          // 0..15  (output-row group)
    const int row0 = blockIdx.x * BM;

    unsigned long long acc2[TM][TN / 2] = {};   // packed f32x2 accumulators

    for (int kt = 0; kt < IN_CH; kt += BK) {
        // ---- load X tile: rows [row0, row0+128), cols [kt, kt+32) -> Xs[k][m]
        #pragma unroll
        for (int l = tid; l < BM * (BK / 4); l += 256) {
            int m = l >> 3;
            int j = l & 7;
            int grow = row0 + m;
            float4 v = make_float4(0.f, 0.f, 0.f, 0.f);
            if (grow < nrows)
                v = *reinterpret_cast<const float4*>(x + (size_t)grow * IN_CH + kt + j * 4);
            Xs[j * 4 + 0][m] = v.x;
            Xs[j * 4 + 1][m] = v.y;
            Xs[j * 4 + 2][m] = v.z;
            Xs[j * 4 + 3][m] = v.w;
        }
        // ---- load W tile: W[o][k] -> Ws[k][o]
        #pragma unroll
        for (int l = tid; l < BN * (BK / 4); l += 256) {
            int o = l >> 3;
            int j = l & 7;
            float4 v = *reinterpret_cast<const float4*>(W + (size_t)o * IN_CH + kt + j * 4);
            Ws[j * 4 + 0][o] = v.x;
            Ws[j * 4 + 1][o] = v.y;
            Ws[j * 4 + 2][o] = v.z;
            Ws[j * 4 + 3][o] = v.w;
        }
        __syncthreads();

        #pragma unroll 8
        for (int k = 0; k < BK; k++) {
            float xf[TM];
            *reinterpret_cast<float4*>(&xf[0]) = *reinterpret_cast<const float4*>(&Xs[k][ty * TM + 0]);
            *reinterpret_cast<float4*>(&xf[4]) = *reinterpret_cast<const float4*>(&Xs[k][ty * TM + 4]);
            // adjacent float pairs in smem == f32x2 packing, read directly as u64
            ulonglong2 w01 = *reinterpret_cast<const ulonglong2*>(&Ws[k][tx * TN + 0]);
            ulonglong2 w23 = *reinterpret_cast<const ulonglong2*>(&Ws[k][tx * TN + 4]);
            unsigned long long wv[4] = { w01.x, w01.y, w23.x, w23.y };
            #pragma unroll
            for (int i = 0; i < TM; i++) {
                unsigned long long xx = bcast2(xf[i]);
                #pragma unroll
                for (int j = 0; j < TN / 2; j++)
                    fma_f32x2(acc2[i][j], xx, wv[j]);
            }
        }
        __syncthreads();   // after last iter: tiles dead, safe to reuse below
    }

    // ---- unpack accumulators
    float acc[TM][TN];
    #pragma unroll
    for (int i = 0; i < TM; i++)
        #pragma unroll
        for (int j = 0; j < TN / 2; j++)
            unpack2(acc2[i][j], acc[i][2 * j], acc[i][2 * j + 1]);

    // ---- epilogue: add bias, store h, compute per-head alpha partials
    float bias[TN], attl[TN], attr[TN];
    *reinterpret_cast<float4*>(&bias[0]) = *reinterpret_cast<const float4*>(b + tx * TN + 0);
    *reinterpret_cast<float4*>(&bias[4]) = *reinterpret_cast<const float4*>(b + tx * TN + 4);
    *reinterpret_cast<float4*>(&attl[0]) = *reinterpret_cast<const float4*>(att_l + tx * TN + 0);
    *reinterpret_cast<float4*>(&attl[4]) = *reinterpret_cast<const float4*>(att_l + tx * TN + 4);
    *reinterpret_cast<float4*>(&attr[0]) = *reinterpret_cast<const float4*>(att_r + tx * TN + 0);
    *reinterpret_cast<float4*>(&attr[4]) = *reinterpret_cast<const float4*>(att_r + tx * TN + 4);

    float* partL = &Xs[0][0];   // [128][16] partial alpha_l
    float* partR = &Ws[0][0];   // [128][16] partial alpha_r

    #pragma unroll
    for (int i = 0; i < TM; i++) {
        int lrow = ty * TM + i;
        int grow = row0 + lrow;
        float vsum[TN];
        float pl = 0.f, pr = 0.f;
        #pragma unroll
        for (int j = 0; j < TN; j++) {
            vsum[j] = acc[i][j] + bias[j];
            pl += vsum[j] * attl[j];
            pr += vsum[j] * attr[j];
        }
        partL[lrow * 16 + tx] = pl;
        partR[lrow * 16 + tx] = pr;
        if (grow < nrows) {
            *reinterpret_cast<float4*>(g_h + (size_t)grow * OUTF + tx * TN + 0) =
                make_float4(vsum[0], vsum[1], vsum[2], vsum[3]);
            *reinterpret_cast<float4*>(g_h + (size_t)grow * OUTF + tx * TN + 4) =
                make_float4(vsum[4], vsum[5], vsum[6], vsum[7]);
        }
    }
    __syncthreads();

    // reduce 4 tx-groups per (row, head)
    #pragma unroll
    for (int o = tid; o < BM * HEADS; o += 256) {
        int lrow = o >> 2;
        int head = o & 3;
        int grow = row0 + lrow;
        if (grow < nrows) {
            float sl = 0.f, sr = 0.f;
            #pragma unroll
            for (int t = 0; t < 4; t++) {
                sl += partL[lrow * 16 + head * 4 + t];
                sr += partR[lrow * 16 + head * 4 + t];
            }
            g_al[(size_t)grow * HEADS + head] = sl;
            g_ar[(size_t)grow * HEADS + head] = sr;
        }
    }
}

// ---------------------------------------------------------------------------
// Kernel 2: edge lift. Persistent grid-stride; 8 edges per warp per iter.
// Lanes 0..7 fetch src/trg indices (streaming loads), broadcast via shuffle;
// 8 independent 512B row gathers issued back-to-back (MLP=8), then 8
// streaming stores. Alpha handled by lanes 0..7, one edge each.
// ---------------------------------------------------------------------------
#define EPW 8   // edges per warp per iteration (N_EDGES % EPW == 0)

__global__ __launch_bounds__(256, 4)
void edge_lift_kernel(const int* __restrict__ src_idx,
                      const int* __restrict__ trg_idx,
                      float* __restrict__ out_alpha,
                      float* __restrict__ out_x,
                      int nedges)
{
    const int lane   = threadIdx.x & 31;
    const int nwarps = (gridDim.x * blockDim.x) >> 5;
    const int gw     = (blockIdx.x * blockDim.x + threadIdx.x) >> 5;

    for (long long base = (long long)gw * EPW; base < nedges;
         base += (long long)nwarps * EPW) {

        int sidx = 0, tidx = 0;
        if (lane < EPW) {
            sidx = __ldcs(src_idx + base + lane);   // streaming: read-once
            tidx = __ldcs(trg_idx + base + lane);
        }

        int s[EPW];
        #pragma unroll
        for (int u = 0; u < EPW; u++)
            s[u] = __shfl_sync(0xffffffffu, sidx, u);

        // EPW independent gathers (MLP=EPW), L2-resident g_h
        float4 v[EPW];
        #pragma unroll
        for (int u = 0; u < EPW; u++)
            v[u] = *reinterpret_cast<const float4*>(g_h + (size_t)s[u] * OUTF + lane * 4);

        #pragma unroll
        for (int u = 0; u < EPW; u++)
            __stcs(reinterpret_cast<float4*>(out_x + (base + u) * OUTF + lane * 4), v[u]);

        if (lane < EPW) {
            float4 al = *reinterpret_cast<const float4*>(g_al + (size_t)sidx * HEADS);
            float4 ar = *reinterpret_cast<const float4*>(g_ar + (size_t)tidx * HEADS);
            float4 a;
            a.x = al.x + ar.x; a.x = (a.x >= 0.f) ? a.x : 0.01f * a.x;
            a.y = al.y + ar.y; a.y = (a.y >= 0.f) ? a.y : 0.01f * a.y;
            a.z = al.z + ar.z; a.z = (a.z >= 0.f) ? a.z : 0.01f * a.z;
            a.w = al.w + ar.w; a.w = (a.w >= 0.f) ? a.w : 0.01f * a.w;
            __stcs(reinterpret_cast<float4*>(out_alpha + (base + lane) * HEADS), a);
        }
    }
}

// ---------------------------------------------------------------------------
// Launch
// ---------------------------------------------------------------------------
extern "C" void kernel_launch(void* const* d_in, const int* in_sizes, int n_in,
                              void* d_out, int out_size)
{
    const float* x     = (const float*)d_in[0];   // [N, 128]
    const float* W     = (const float*)d_in[1];   // [128, 128]
    const float* b     = (const float*)d_in[2];   // [128]
    const float* att_l = (const float*)d_in[3];   // [1,4,32] -> flat 128
    const float* att_r = (const float*)d_in[4];   // [1,4,32] -> flat 128
    const int*   src   = (const int*)d_in[5];     // [E]
    const int*   trg   = (const int*)d_in[6];     // [E]

    float* out_alpha = (float*)d_out;                                   // [E, 4]
    float* out_x     = (float*)d_out + (size_t)N_EDGES * HEADS;         // [E, 4, 32]

    // 1) projection GEMM into g_h (+ fused alpha_l/alpha_r)
    int gemm_blocks = (N_NODES + BM - 1) / BM;                 // 782
    gemm_proj_kernel<<<gemm_blocks, 256>>>(x, W, b, att_l, att_r, N_NODES);

    // 2) edge lift: persistent, 4 CTAs/SM (launch_bounds-pinned), grid-stride
    int edge_blocks = 148 * 4;                                 // 592
    edge_lift_kernel<<<edge_blocks, 256>>>(src, trg, out_alpha, out_x, N_EDGES);
}

// round 9
// speedup vs baseline: 1.1366x; 1.0222x over previous
#include <cuda_runtime.h>
#include <cuda_bf16.h>
#include <cstdint>

// Problem constants
#define N_NODES 100000
#define N_EDGES 1638400
#define IN_CH   128
#define HEADS   4
#define OUT_CH  32
#define OUTF    (HEADS * OUT_CH)   // 128

// Scratch (allowed: __device__ globals, no allocation)
__device__ float g_h [(size_t)N_NODES * OUTF];   // 51.2 MB, L2-resident
__device__ float g_al[(size_t)N_NODES * HEADS];
__device__ float g_ar[(size_t)N_NODES * HEADS];

// ---------------------------------------------------------------------------
// Packed f32x2 FMA (sm_100+): 2 MACs per fma-pipe issue slot.
// ---------------------------------------------------------------------------
__device__ __forceinline__ void fma_f32x2(unsigned long long& d,
                                          unsigned long long a,
                                          unsigned long long b) {
    asm("fma.rn.f32x2 %0, %1, %2, %0;" : "+l"(d) : "l"(a), "l"(b));
}
__device__ __forceinline__ unsigned long long bcast2(float v) {
    unsigned long long r;
    unsigned u = __float_as_uint(v);
    asm("mov.b64 %0, {%1, %1};" : "=l"(r) : "r"(u));
    return r;
}
__device__ __forceinline__ void unpack2(unsigned long long v, float& lo, float& hi) {
    unsigned a, b;
    asm("mov.b64 {%0, %1}, %2;" : "=r"(a), "=r"(b) : "l"(v));
    lo = __uint_as_float(a);
    hi = __uint_as_float(b);
}

// ---------------------------------------------------------------------------
// Kernel 1: h = x @ W^T + b   (M=100000, K=128, N=128)
// BM=128, BN=128, BK=32, 256 threads, 8x8 microtile, FFMA2 microloop.
// Epilogue fuses per-node attention scores alpha_l / alpha_r.
// ---------------------------------------------------------------------------
#define BM 128
#define BN 128
#define BK 32
#define TM 8
#define TN 8

__global__ __launch_bounds__(256, 2)
void gemm_proj_kernel(const float* __restrict__ x,
                      const float* __restrict__ W,
                      const float* __restrict__ b,
                      const float* __restrict__ att_l,
                      const float* __restrict__ att_r,
                      int nrows)
{
    __shared__ __align__(16) float Xs[BK][BM];   // k-major; reused in epilogue
    __shared__ __align__(16) float Ws[BK][BN];   // k-major; reused in epilogue

    const int tid = threadIdx.x;
    const int tx  = tid & 15;          // 0..15  (output-col group)
    const int ty  = tid >> 4;          // 0..15  (output-row group)
    const int row0 = blockIdx.x * BM;

    unsigned long long acc2[TM][TN / 2] = {};   // packed f32x2 accumulators

    for (int kt = 0; kt < IN_CH; kt += BK) {
        // ---- load X tile: rows [row0, row0+128), cols [kt, kt+32) -> Xs[k][m]
        #pragma unroll
        for (int l = tid; l < BM * (BK / 4); l += 256) {
            int m = l >> 3;
            int j = l & 7;
            int grow = row0 + m;
            float4 v = make_float4(0.f, 0.f, 0.f, 0.f);
            if (grow < nrows)
                v = *reinterpret_cast<const float4*>(x + (size_t)grow * IN_CH + kt + j * 4);
            Xs[j * 4 + 0][m] = v.x;
            Xs[j * 4 + 1][m] = v.y;
            Xs[j * 4 + 2][m] = v.z;
            Xs[j * 4 + 3][m] = v.w;
        }
        // ---- load W tile: W[o][k] -> Ws[k][o]
        #pragma unroll
        for (int l = tid; l < BN * (BK / 4); l += 256) {
            int o = l >> 3;
            int j = l & 7;
            float4 v = *reinterpret_cast<const float4*>(W + (size_t)o * IN_CH + kt + j * 4);
            Ws[j * 4 + 0][o] = v.x;
            Ws[j * 4 + 1][o] = v.y;
            Ws[j * 4 + 2][o] = v.z;
            Ws[j * 4 + 3][o] = v.w;
        }
        __syncthreads();

        #pragma unroll 8
        for (int k = 0; k < BK; k++) {
            float xf[TM];
            *reinterpret_cast<float4*>(&xf[0]) = *reinterpret_cast<const float4*>(&Xs[k][ty * TM + 0]);
            *reinterpret_cast<float4*>(&xf[4]) = *reinterpret_cast<const float4*>(&Xs[k][ty * TM + 4]);
            // adjacent float pairs in smem == f32x2 packing, read directly as u64
            ulonglong2 w01 = *reinterpret_cast<const ulonglong2*>(&Ws[k][tx * TN + 0]);
            ulonglong2 w23 = *reinterpret_cast<const ulonglong2*>(&Ws[k][tx * TN + 4]);
            unsigned long long wv[4] = { w01.x, w01.y, w23.x, w23.y };
            #pragma unroll
            for (int i = 0; i < TM; i++) {
                unsigned long long xx = bcast2(xf[i]);
                #pragma unroll
                for (int j = 0; j < TN / 2; j++)
                    fma_f32x2(acc2[i][j], xx, wv[j]);
            }
        }
        __syncthreads();   // after last iter: tiles dead, safe to reuse below
    }

    // ---- unpack accumulators
    float acc[TM][TN];
    #pragma unroll
    for (int i = 0; i < TM; i++)
        #pragma unroll
        for (int j = 0; j < TN / 2; j++)
            unpack2(acc2[i][j], acc[i][2 * j], acc[i][2 * j + 1]);

    // ---- epilogue: add bias, store h, compute per-head alpha partials
    float bias[TN], attl[TN], attr[TN];
    *reinterpret_cast<float4*>(&bias[0]) = *reinterpret_cast<const float4*>(b + tx * TN + 0);
    *reinterpret_cast<float4*>(&bias[4]) = *reinterpret_cast<const float4*>(b + tx * TN + 4);
    *reinterpret_cast<float4*>(&attl[0]) = *reinterpret_cast<const float4*>(att_l + tx * TN + 0);
    *reinterpret_cast<float4*>(&attl[4]) = *reinterpret_cast<const float4*>(att_l + tx * TN + 4);
    *reinterpret_cast<float4*>(&attr[0]) = *reinterpret_cast<const float4*>(att_r + tx * TN + 0);
    *reinterpret_cast<float4*>(&attr[4]) = *reinterpret_cast<const float4*>(att_r + tx * TN + 4);

    float* partL = &Xs[0][0];   // [128][16] partial alpha_l
    float* partR = &Ws[0][0];   // [128][16] partial alpha_r

    #pragma unroll
    for (int i = 0; i < TM; i++) {
        int lrow = ty * TM + i;
        int grow = row0 + lrow;
        float vsum[TN];
        float pl = 0.f, pr = 0.f;
        #pragma unroll
        for (int j = 0; j < TN; j++) {
            vsum[j] = acc[i][j] + bias[j];
            pl += vsum[j] * attl[j];
            pr += vsum[j] * attr[j];
        }
        partL[lrow * 16 + tx] = pl;
        partR[lrow * 16 + tx] = pr;
        if (grow < nrows) {
            *reinterpret_cast<float4*>(g_h + (size_t)grow * OUTF + tx * TN + 0) =
                make_float4(vsum[0], vsum[1], vsum[2], vsum[3]);
            *reinterpret_cast<float4*>(g_h + (size_t)grow * OUTF + tx * TN + 4) =
                make_float4(vsum[4], vsum[5], vsum[6], vsum[7]);
        }
    }
    __syncthreads();

    // reduce 4 tx-groups per (row, head)
    #pragma unroll
    for (int o = tid; o < BM * HEADS; o += 256) {
        int lrow = o >> 2;
        int head = o & 3;
        int grow = row0 + lrow;
        if (grow < nrows) {
            float sl = 0.f, sr = 0.f;
            #pragma unroll
            for (int t = 0; t < 4; t++) {
                sl += partL[lrow * 16 + head * 4 + t];
                sr += partR[lrow * 16 + head * 4 + t];
            }
            g_al[(size_t)grow * HEADS + head] = sl;
            g_ar[(size_t)grow * HEADS + head] = sr;
        }
    }
}

// ---------------------------------------------------------------------------
// Kernel 2: edge lift. Persistent grid-stride; 8 edges per warp per iter.
// Lanes 0..7 fetch src/trg indices (streaming loads), broadcast via shuffle;
// 8 independent 512B row gathers issued back-to-back (MLP=8), then 8
// streaming stores. Alpha handled by lanes 0..7, one edge each.
// ---------------------------------------------------------------------------
#define EPW 8   // edges per warp per iteration (N_EDGES % EPW == 0)

__global__ __launch_bounds__(256, 4)
void edge_lift_kernel(const int* __restrict__ src_idx,
                      const int* __restrict__ trg_idx,
                      float* __restrict__ out_alpha,
                      float* __restrict__ out_x,
                      int nedges)
{
    const int lane   = threadIdx.x & 31;
    const int nwarps = (gridDim.x * blockDim.x) >> 5;
    const int gw     = (blockIdx.x * blockDim.x + threadIdx.x) >> 5;

    for (long long base = (long long)gw * EPW; base < nedges;
         base += (long long)nwarps * EPW) {

        int sidx = 0, tidx = 0;
        if (lane < EPW) {
            sidx = __ldcs(src_idx + base + lane);   // streaming: read-once
            tidx = __ldcs(trg_idx + base + lane);
        }

        int s[EPW];
        #pragma unroll
        for (int u = 0; u < EPW; u++)
            s[u] = __shfl_sync(0xffffffffu, sidx, u);

        // EPW independent gathers (MLP=EPW), L2-resident g_h
        float4 v[EPW];
        #pragma unroll
        for (int u = 0; u < EPW; u++)
            v[u] = *reinterpret_cast<const float4*>(g_h + (size_t)s[u] * OUTF + lane * 4);

        #pragma unroll
        for (int u = 0; u < EPW; u++)
            __stcs(reinterpret_cast<float4*>(out_x + (base + u) * OUTF + lane * 4), v[u]);

        if (lane < EPW) {
            float4 al = *reinterpret_cast<const float4*>(g_al + (size_t)sidx * HEADS);
            float4 ar = *reinterpret_cast<const float4*>(g_ar + (size_t)tidx * HEADS);
            float4 a;
            a.x = al.x + ar.x; a.x = (a.x >= 0.f) ? a.x : 0.01f * a.x;
            a.y = al.y + ar.y; a.y = (a.y >= 0.f) ? a.y : 0.01f * a.y;
            a.z = al.z + ar.z; a.z = (a.z >= 0.f) ? a.z : 0.01f * a.z;
            a.w = al.w + ar.w; a.w = (a.w >= 0.f) ? a.w : 0.01f * a.w;
            __stcs(reinterpret_cast<float4*>(out_alpha + (base + lane) * HEADS), a);
        }
    }
}

// ---------------------------------------------------------------------------
// Launch
// ---------------------------------------------------------------------------
extern "C" void kernel_launch(void* const* d_in, const int* in_sizes, int n_in,
                              void* d_out, int out_size)
{
    const float* x     = (const float*)d_in[0];   // [N, 128]
    const float* W     = (const float*)d_in[1];   // [128, 128]
    const float* b     = (const float*)d_in[2];   // [128]
    const float* att_l = (const float*)d_in[3];   // [1,4,32] -> flat 128
    const float* att_r = (const float*)d_in[4];   // [1,4,32] -> flat 128
    const int*   src   = (const int*)d_in[5];     // [E]
    const int*   trg   = (const int*)d_in[6];     // [E]

    float* out_alpha = (float*)d_out;                                   // [E, 4]
    float* out_x     = (float*)d_out + (size_t)N_EDGES * HEADS;         // [E, 4, 32]

    // 1) projection GEMM into g_h (+ fused alpha_l/alpha_r)
    int gemm_blocks = (N_NODES + BM - 1) / BM;                 // 782
    gemm_proj_kernel<<<gemm_blocks, 256>>>(x, W, b, att_l, att_r, N_NODES);

    // 2) edge lift: persistent, 4 CTAs/SM (launch_bounds-pinned), grid-stride
    int edge_blocks = 148 * 4;                                 // 592
    edge_lift_kernel<<<edge_blocks, 256>>>(src, trg, out_alpha, out_x, N_EDGES);
}

// round 10
// speedup vs baseline: 1.1429x; 1.0055x over previous
#include <cuda_runtime.h>
#include <cuda_bf16.h>
#include <cstdint>

// Problem constants
#define N_NODES 100000
#define N_EDGES 1638400
#define IN_CH   128
#define HEADS   4
#define OUT_CH  32
#define OUTF    (HEADS * OUT_CH)   // 128

// Scratch (allowed: __device__ globals, no allocation)
__device__ float g_h [(size_t)N_NODES * OUTF];   // 51.2 MB, L2-resident
__device__ float g_al[(size_t)N_NODES * HEADS];
__device__ float g_ar[(size_t)N_NODES * HEADS];

// ---------------------------------------------------------------------------
// Packed f32x2 FMA (sm_100+): 2 MACs per fma-pipe issue slot.
// ---------------------------------------------------------------------------
__device__ __forceinline__ void fma_f32x2(unsigned long long& d,
                                          unsigned long long a,
                                          unsigned long long b) {
    asm("fma.rn.f32x2 %0, %1, %2, %0;" : "+l"(d) : "l"(a), "l"(b));
}
__device__ __forceinline__ unsigned long long bcast2(float v) {
    unsigned long long r;
    unsigned u = __float_as_uint(v);
    asm("mov.b64 %0, {%1, %1};" : "=l"(r) : "r"(u));
    return r;
}
__device__ __forceinline__ void unpack2(unsigned long long v, float& lo, float& hi) {
    unsigned a, b;
    asm("mov.b64 {%0, %1}, %2;" : "=r"(a), "=r"(b) : "l"(v));
    lo = __uint_as_float(a);
    hi = __uint_as_float(b);
}

// ---------------------------------------------------------------------------
// Kernel 1: h = x @ W^T + b   (M=100000, K=128, N=128)
// BM=128, BN=128, BK=32, 256 threads, 8x8 microtile, FFMA2 microloop.
// Epilogue fuses per-node attention scores alpha_l / alpha_r.
// ---------------------------------------------------------------------------
#define BM 128
#define BN 128
#define BK 32
#define TM 8
#define TN 8

__global__ __launch_bounds__(256, 2)
void gemm_proj_kernel(const float* __restrict__ x,
                      const float* __restrict__ W,
                      const float* __restrict__ b,
                      const float* __restrict__ att_l,
                      const float* __restrict__ att_r,
                      int nrows)
{
    __shared__ __align__(16) float Xs[BK][BM];   // k-major; reused in epilogue
    __shared__ __align__(16) float Ws[BK][BN];   // k-major; reused in epilogue

    const int tid = threadIdx.x;
    const int tx  = tid & 15;          // 0..15  (output-col group)
    const int ty  = tid >> 4;          // 0..15  (output-row group)
    const int row0 = blockIdx.x * BM;

    unsigned long long acc2[TM][TN / 2] = {};   // packed f32x2 accumulators

    for (int kt = 0; kt < IN_CH; kt += BK) {
        // ---- load X tile: rows [row0, row0+128), cols [kt, kt+32) -> Xs[k][m]
        #pragma unroll
        for (int l = tid; l < BM * (BK / 4); l += 256) {
            int m = l >> 3;
            int j = l & 7;
            int grow = row0 + m;
            float4 v = make_float4(0.f, 0.f, 0.f, 0.f);
            if (grow < nrows)
                v = *reinterpret_cast<const float4*>(x + (size_t)grow * IN_CH + kt + j * 4);
            Xs[j * 4 + 0][m] = v.x;
            Xs[j * 4 + 1][m] = v.y;
            Xs[j * 4 + 2][m] = v.z;
            Xs[j * 4 + 3][m] = v.w;
        }
        // ---- load W tile: W[o][k] -> Ws[k][o]
        #pragma unroll
        for (int l = tid; l < BN * (BK / 4); l += 256) {
            int o = l >> 3;
            int j = l & 7;
            float4 v = *reinterpret_cast<const float4*>(W + (size_t)o * IN_CH + kt + j * 4);
            Ws[j * 4 + 0][o] = v.x;
            Ws[j * 4 + 1][o] = v.y;
            Ws[j * 4 + 2][o] = v.z;
            Ws[j * 4 + 3][o] = v.w;
        }
        __syncthreads();

        #pragma unroll 8
        for (int k = 0; k < BK; k++) {
            float xf[TM];
            *reinterpret_cast<float4*>(&xf[0]) = *reinterpret_cast<const float4*>(&Xs[k][ty * TM + 0]);
            *reinterpret_cast<float4*>(&xf[4]) = *reinterpret_cast<const float4*>(&Xs[k][ty * TM + 4]);
            // adjacent float pairs in smem == f32x2 packing, read directly as u64
            ulonglong2 w01 = *reinterpret_cast<const ulonglong2*>(&Ws[k][tx * TN + 0]);
            ulonglong2 w23 = *reinterpret_cast<const ulonglong2*>(&Ws[k][tx * TN + 4]);
            unsigned long long wv[4] = { w01.x, w01.y, w23.x, w23.y };
            #pragma unroll
            for (int i = 0; i < TM; i++) {
                unsigned long long xx = bcast2(xf[i]);
                #pragma unroll
                for (int j = 0; j < TN / 2; j++)
                    fma_f32x2(acc2[i][j], xx, wv[j]);
            }
        }
        __syncthreads();   // after last iter: tiles dead, safe to reuse below
    }

    // ---- unpack accumulators
    float acc[TM][TN];
    #pragma unroll
    for (int i = 0; i < TM; i++)
        #pragma unroll
        for (int j = 0; j < TN / 2; j++)
            unpack2(acc2[i][j], acc[i][2 * j], acc[i][2 * j + 1]);

    // ---- epilogue: add bias, store h, compute per-head alpha partials
    float bias[TN], attl[TN], attr[TN];
    *reinterpret_cast<float4*>(&bias[0]) = *reinterpret_cast<const float4*>(b + tx * TN + 0);
    *reinterpret_cast<float4*>(&bias[4]) = *reinterpret_cast<const float4*>(b + tx * TN + 4);
    *reinterpret_cast<float4*>(&attl[0]) = *reinterpret_cast<const float4*>(att_l + tx * TN + 0);
    *reinterpret_cast<float4*>(&attl[4]) = *reinterpret_cast<const float4*>(att_l + tx * TN + 4);
    *reinterpret_cast<float4*>(&attr[0]) = *reinterpret_cast<const float4*>(att_r + tx * TN + 0);
    *reinterpret_cast<float4*>(&attr[4]) = *reinterpret_cast<const float4*>(att_r + tx * TN + 4);

    float* partL = &Xs[0][0];   // [128][16] partial alpha_l
    float* partR = &Ws[0][0];   // [128][16] partial alpha_r

    #pragma unroll
    for (int i = 0; i < TM; i++) {
        int lrow = ty * TM + i;
        int grow = row0 + lrow;
        float vsum[TN];
        float pl = 0.f, pr = 0.f;
        #pragma unroll
        for (int j = 0; j < TN; j++) {
            vsum[j] = acc[i][j] + bias[j];
            pl += vsum[j] * attl[j];
            pr += vsum[j] * attr[j];
        }
        partL[lrow * 16 + tx] = pl;
        partR[lrow * 16 + tx] = pr;
        if (grow < nrows) {
            *reinterpret_cast<float4*>(g_h + (size_t)grow * OUTF + tx * TN + 0) =
                make_float4(vsum[0], vsum[1], vsum[2], vsum[3]);
            *reinterpret_cast<float4*>(g_h + (size_t)grow * OUTF + tx * TN + 4) =
                make_float4(vsum[4], vsum[5], vsum[6], vsum[7]);
        }
    }
    __syncthreads();

    // reduce 4 tx-groups per (row, head)
    #pragma unroll
    for (int o = tid; o < BM * HEADS; o += 256) {
        int lrow = o >> 2;
        int head = o & 3;
        int grow = row0 + lrow;
        if (grow < nrows) {
            float sl = 0.f, sr = 0.f;
            #pragma unroll
            for (int t = 0; t < 4; t++) {
                sl += partL[lrow * 16 + head * 4 + t];
                sr += partR[lrow * 16 + head * 4 + t];
            }
            g_al[(size_t)grow * HEADS + head] = sl;
            g_ar[(size_t)grow * HEADS + head] = sr;
        }
    }
}

// ---------------------------------------------------------------------------
// Kernel 2: edge lift. Persistent grid-stride; 8 edges per warp per iter.
// Lanes 0..7 fetch src/trg indices (streaming loads), broadcast via shuffle;
// 8 independent 512B row gathers issued back-to-back (MLP=8), then 8
// streaming stores. Alpha handled by lanes 0..7, one edge each.
// ---------------------------------------------------------------------------
#define EPW 8   // edges per warp per iteration (N_EDGES % EPW == 0)

__global__ __launch_bounds__(256, 4)
void edge_lift_kernel(const int* __restrict__ src_idx,
                      const int* __restrict__ trg_idx,
                      float* __restrict__ out_alpha,
                      float* __restrict__ out_x,
                      int nedges)
{
    const int lane   = threadIdx.x & 31;
    const int nwarps = (gridDim.x * blockDim.x) >> 5;
    const int gw     = (blockIdx.x * blockDim.x + threadIdx.x) >> 5;

    for (long long base = (long long)gw * EPW; base < nedges;
         base += (long long)nwarps * EPW) {

        int sidx = 0, tidx = 0;
        if (lane < EPW) {
            sidx = __ldcs(src_idx + base + lane);   // streaming: read-once
            tidx = __ldcs(trg_idx + base + lane);
        }

        int s[EPW];
        #pragma unroll
        for (int u = 0; u < EPW; u++)
            s[u] = __shfl_sync(0xffffffffu, sidx, u);

        // EPW independent gathers (MLP=EPW), L2-resident g_h
        float4 v[EPW];
        #pragma unroll
        for (int u = 0; u < EPW; u++)
            v[u] = *reinterpret_cast<const float4*>(g_h + (size_t)s[u] * OUTF + lane * 4);

        #pragma unroll
        for (int u = 0; u < EPW; u++)
            __stcs(reinterpret_cast<float4*>(out_x + (base + u) * OUTF + lane * 4), v[u]);

        if (lane < EPW) {
            float4 al = *reinterpret_cast<const float4*>(g_al + (size_t)sidx * HEADS);
            float4 ar = *reinterpret_cast<const float4*>(g_ar + (size_t)tidx * HEADS);
            float4 a;
            a.x = al.x + ar.x; a.x = (a.x >= 0.f) ? a.x : 0.01f * a.x;
            a.y = al.y + ar.y; a.y = (a.y >= 0.f) ? a.y : 0.01f * a.y;
            a.z = al.z + ar.z; a.z = (a.z >= 0.f) ? a.z : 0.01f * a.z;
            a.w = al.w + ar.w; a.w = (a.w >= 0.f) ? a.w : 0.01f * a.w;
            __stcs(reinterpret_cast<float4*>(out_alpha + (base + lane) * HEADS), a);
        }
    }
}

// ---------------------------------------------------------------------------
// Launch
// ---------------------------------------------------------------------------
extern "C" void kernel_launch(void* const* d_in, const int* in_sizes, int n_in,
                              void* d_out, int out_size)
{
    const float* x     = (const float*)d_in[0];   // [N, 128]
    const float* W     = (const float*)d_in[1];   // [128, 128]
    const float* b     = (const float*)d_in[2];   // [128]
    const float* att_l = (const float*)d_in[3];   // [1,4,32] -> flat 128
    const float* att_r = (const float*)d_in[4];   // [1,4,32] -> flat 128
    const int*   src   = (const int*)d_in[5];     // [E]
    const int*   trg   = (const int*)d_in[6];     // [E]

    float* out_alpha = (float*)d_out;                                   // [E, 4]
    float* out_x     = (float*)d_out + (size_t)N_EDGES * HEADS;         // [E, 4, 32]

    // 1) projection GEMM into g_h (+ fused alpha_l/alpha_r)
    int gemm_blocks = (N_NODES + BM - 1) / BM;                 // 782
    gemm_proj_kernel<<<gemm_blocks, 256>>>(x, W, b, att_l, att_r, N_NODES);

    // 2) edge lift: persistent, 4 CTAs/SM (launch_bounds-pinned), grid-stride
    int edge_blocks = 148 * 4;                                 // 592
    edge_lift_kernel<<<edge_blocks, 256>>>(src, trg, out_alpha, out_x, N_EDGES);
}